// round 1
// baseline (speedup 1.0000x reference)
#include <cuda_runtime.h>
#include <math.h>

// Problem constants (fixed by setup_inputs)
#define BATCH   8
#define CHAN    256
#define NPIX    16384       // 128*128
#define NITER   16
#define TILE_N  128
#define NTHR    256

// d_out layout: reprVecs [16,8,256] | sims [16,8,16384] | selpos [8,16384]
#define OFF_REPR   0
#define OFF_SIMS   (NITER*BATCH*CHAN)                 // 32768
#define OFF_SELPOS (OFF_SIMS + NITER*BATCH*NPIX)      // 2129920

// Scratch (no allocations allowed -> __device__ globals)
__device__ float g_score[BATCH*NPIX];
__device__ float g_accum[BATCH*CHAN];
__device__ float g_sumsim[BATCH];
__device__ int   g_ind[BATCH];

// ---------------------------------------------------------------------------
__global__ void init_kernel(float* __restrict__ selpos) {
    int i = blockIdx.x * blockDim.x + threadIdx.x;
    if (i < BATCH*NPIX) selpos[i] = 0.0f;
    if (i < BATCH*CHAN) g_accum[i] = 0.0f;
    if (i < BATCH)      g_sumsim[i] = 0.0f;
}

// ---------------------------------------------------------------------------
// One block per batch. Does (a) epilogue of iteration iter-1 (normalize repr
// accumulator), (b) index selection for iteration iter (argmax of score, or
// N/2 at iter 0), (c) selpos increment, (d) reset accumulators.
// iter == NITER means "final epilogue only".
__global__ void select_kernel(int iter, float* __restrict__ repr_out,
                              float* __restrict__ selpos) {
    int b   = blockIdx.x;
    int tid = threadIdx.x;
    __shared__ float s_val[NTHR];
    __shared__ int   s_idx[NTHR];

    if (iter > 0) {
        // epilogue for iter-1: repr = accum / sumsim, reset accum
        float inv = 1.0f / g_sumsim[b];
        repr_out[((size_t)(iter-1)*BATCH + b)*CHAN + tid] =
            g_accum[b*CHAN + tid] * inv;
        g_accum[b*CHAN + tid] = 0.0f;
    }

    if (iter < NITER) {
        int ind;
        if (iter == 0) {
            ind = NPIX / 2;
            __syncthreads();
        } else {
            // argmax over score[b][:], lowest index on ties (jnp.argmax)
            const float* sc = g_score + (size_t)b*NPIX;
            float best = -1e30f; int bi = 0;
            #pragma unroll 8
            for (int k = tid; k < NPIX; k += NTHR) {
                float v = sc[k];
                if (v > best) { best = v; bi = k; }   // ascending k -> first max
            }
            s_val[tid] = best; s_idx[tid] = bi;
            __syncthreads();
            for (int s = NTHR/2; s > 0; s >>= 1) {
                if (tid < s) {
                    float v2 = s_val[tid+s]; int i2 = s_idx[tid+s];
                    if (v2 > s_val[tid] || (v2 == s_val[tid] && i2 < s_idx[tid])) {
                        s_val[tid] = v2; s_idx[tid] = i2;
                    }
                }
                __syncthreads();
            }
            ind = s_idx[0];
        }
        // all threads have passed a barrier after reading g_sumsim (iter>0 path)
        if (tid == 0) {
            g_ind[b] = ind;
            selpos[(size_t)b*NPIX + ind] += 1.0f;
            g_sumsim[b] = 0.0f;
        }
    }
}

// ---------------------------------------------------------------------------
// Main fused kernel: one block per (128-pixel tile, batch).
// Stages the [256 c x 128 n] fp32 tile (128 KB) in SMEM once; both the
// distance pass and the sim-weighted channel reduction read from SMEM.
// HBM traffic: exactly one read of x per iteration.
extern "C" __global__ void __launch_bounds__(NTHR, 1)
main_kernel(int iter, const float* __restrict__ x,
            float* __restrict__ sims_out) {
    extern __shared__ float xs[];          // [CHAN][TILE_N] = 128 KB
    __shared__ float s_rv[CHAN];
    __shared__ float s_sim[TILE_N];
    __shared__ float s_part[NTHR];
    __shared__ float s_blocksum;

    const int b    = blockIdx.y;
    const int n0   = blockIdx.x * TILE_N;
    const int tid  = threadIdx.x;
    const int lane = tid & 31;
    const int w    = tid >> 5;

    const float* __restrict__ xb = x + (size_t)b * CHAN * NPIX;
    const int ind = g_ind[b];

    // representative vector gather (one element per thread, L2-served)
    s_rv[tid] = xb[(size_t)tid * NPIX + ind];
    if (tid == 0) s_blocksum = 0.0f;

    // ---- stage tile: float4, coalesced (n contiguous in gmem) ----
    // xs layout [c][n]; float4 row = 32 elements -> idx4 = c*32 + n4
    const int NITER4 = (CHAN * TILE_N / 4) / NTHR;   // 32
    #pragma unroll 8
    for (int it = 0; it < NITER4; it++) {
        int idx4 = tid + it * NTHR;
        int c    = idx4 >> 5;
        int n4   = idx4 & 31;
        float4 v = *(const float4*)(xb + (size_t)c * NPIX + n0 + n4 * 4);
        ((float4*)xs)[idx4] = v;
    }
    __syncthreads();

    // ---- distance: each pixel split across 2 threads (128 channels each) ----
    {
        int n    = tid & (TILE_N - 1);
        int base = (tid >> 7) * 128;        // 0 or 128
        float acc = 0.0f;
        #pragma unroll 8
        for (int c = base; c < base + 128; c++) {
            float d = xs[c * TILE_N + n] - s_rv[c];
            acc = fmaf(d, d, acc);
        }
        s_part[tid] = acc;
    }
    __syncthreads();

    if (tid < TILE_N) {
        float ssq = s_part[tid] + s_part[tid + 128];
        float d   = sqrtf(ssq + 1e-12f);
        float sim = expf(-d * 0.05f);       // exp(-d/20)
        s_sim[tid] = sim;
        int nn = n0 + tid;
        sims_out[((size_t)iter * BATCH + b) * NPIX + nn] = sim;
        // score update (prior is dead: replaced at iter 0)
        float sc = 1.0f - sim;
        if (iter > 0) sc *= g_score[(size_t)b * NPIX + nn];
        g_score[(size_t)b * NPIX + nn] = sc;
        // block-local sim sum
        float ws = sim;
        #pragma unroll
        for (int o = 16; o; o >>= 1) ws += __shfl_down_sync(0xffffffffu, ws, o);
        if (lane == 0) atomicAdd(&s_blocksum, ws);
    }
    __syncthreads();
    if (tid == 0) atomicAdd(&g_sumsim[b], s_blocksum);

    // ---- repr accumulation: warp w owns channels [w*32, w*32+32) ----
    #pragma unroll 4
    for (int ci = 0; ci < 32; ci++) {
        int c = w * 32 + ci;
        float a = 0.0f;
        #pragma unroll
        for (int k = 0; k < 4; k++) {
            int j = lane + 32 * k;
            a = fmaf(s_sim[j], xs[c * TILE_N + j], a);
        }
        #pragma unroll
        for (int o = 16; o; o >>= 1) a += __shfl_down_sync(0xffffffffu, a, o);
        if (lane == 0) atomicAdd(&g_accum[b * CHAN + c], a);
    }
}

// ---------------------------------------------------------------------------
extern "C" void kernel_launch(void* const* d_in, const int* in_sizes, int n_in,
                              void* d_out, int out_size) {
    const float* x = (const float*)d_in[0];
    float* out     = (float*)d_out;
    float* repr_out = out + OFF_REPR;
    float* sims_out = out + OFF_SIMS;
    float* selpos   = out + OFF_SELPOS;

    cudaFuncSetAttribute(main_kernel,
                         cudaFuncAttributeMaxDynamicSharedMemorySize,
                         CHAN * TILE_N * (int)sizeof(float));

    init_kernel<<<(BATCH*NPIX + NTHR - 1) / NTHR, NTHR>>>(selpos);

    dim3 grid(NPIX / TILE_N, BATCH);
    for (int i = 0; i < NITER; i++) {
        select_kernel<<<BATCH, NTHR>>>(i, repr_out, selpos);
        main_kernel<<<grid, NTHR, CHAN * TILE_N * sizeof(float)>>>(i, x, sims_out);
    }
    // final epilogue for iteration 15
    select_kernel<<<BATCH, NTHR>>>(NITER, repr_out, selpos);
}